// round 3
// baseline (speedup 1.0000x reference)
#include <cuda_runtime.h>
#include <cuda_bf16.h>

#define N_NODES 50000
#define N_EDGES 800000
#define IN_FEAT 512
#define HIDDEN  64
#define N_CLASS 16
#define KC      32
#define RB      256   // rows per block in gemm1

// Scratch (device globals — no allocation allowed)
__device__ float g_h0[N_NODES * HIDDEN];   // x @ W1
__device__ float g_h [N_NODES * HIDDEN];   // relu(A @ h0 + b1)
__device__ float g_z [N_NODES * N_CLASS];  // h @ W2
__device__ float g_l [N_NODES * N_CLASS];  // A @ z + b2 (logits)
// CSR by destination
__device__ int g_deg [N_NODES];
__device__ int g_off [N_NODES];
__device__ int g_cur [N_NODES];
__device__ int g_eidx[N_EDGES];

__device__ __forceinline__ void red_add_v4(float* p, float4 v) {
    asm volatile("red.global.add.v4.f32 [%0], {%1,%2,%3,%4};"
                 :: "l"(p), "f"(v.x), "f"(v.y), "f"(v.z), "f"(v.w)
                 : "memory");
}

// ---------------------------------------------------------------------------
// zero: g_deg <- 0, g_l <- broadcast b2
// ---------------------------------------------------------------------------
__global__ void zero_kernel(const float* __restrict__ b2) {
    int i = blockIdx.x * blockDim.x + threadIdx.x;
    if (i < N_NODES) g_deg[i] = 0;
    if (i < N_NODES * N_CLASS) g_l[i] = b2[i & (N_CLASS - 1)];
}

// ---------------------------------------------------------------------------
// hist: degree count by dst
// ---------------------------------------------------------------------------
__global__ void hist_kernel(const int* __restrict__ dst) {
    int e = blockIdx.x * blockDim.x + threadIdx.x;
    if (e < N_EDGES) atomicAdd(&g_deg[dst[e]], 1);
}

// ---------------------------------------------------------------------------
// scan: exclusive prefix sum of g_deg -> g_off, copy to g_cur. Single block.
// ---------------------------------------------------------------------------
#define SCAN_T 1024
#define CHUNK  49   // 1024*49 = 50176 >= 50000
__global__ __launch_bounds__(SCAN_T)
void scan_kernel() {
    __shared__ int part[SCAN_T];
    int tid = threadIdx.x;
    int base = tid * CHUNK;
    int s = 0;
    for (int i = 0; i < CHUNK; i++) {
        int idx = base + i;
        if (idx < N_NODES) {
            int v = g_deg[idx];
            g_off[idx] = s;       // local exclusive prefix
            s += v;
        }
    }
    part[tid] = s;
    __syncthreads();
    // Hillis-Steele inclusive scan over 1024 partials
    for (int d = 1; d < SCAN_T; d <<= 1) {
        int o = (tid >= d) ? part[tid - d] : 0;
        __syncthreads();
        part[tid] += o;
        __syncthreads();
    }
    int off = part[tid] - s;   // exclusive offset for this thread's chunk
    for (int i = 0; i < CHUNK; i++) {
        int idx = base + i;
        if (idx < N_NODES) {
            int v = g_off[idx] + off;
            g_off[idx] = v;
            g_cur[idx] = v;
        }
    }
}

// ---------------------------------------------------------------------------
// fill: scatter edge ids into CSR
// ---------------------------------------------------------------------------
__global__ void fill_kernel(const int* __restrict__ dst) {
    int e = blockIdx.x * blockDim.x + threadIdx.x;
    if (e < N_EDGES) {
        int pos = atomicAdd(&g_cur[dst[e]], 1);
        g_eidx[pos] = e;
    }
}

// ---------------------------------------------------------------------------
// GEMM1: g_h0 = x @ W1   (50000x512 @ 512x64)
// Block: 256 rows x 64 cols, 256 threads (32 x 8), 8x8 reg tile per thread.
// ---------------------------------------------------------------------------
__global__ __launch_bounds__(256, 2)
void gemm1_kernel(const float* __restrict__ x, const float* __restrict__ W1) {
    __shared__ float  xs[KC][RB];          // 32 KB, transposed
    __shared__ float4 ws[KC][HIDDEN / 4];  // 8 KB

    const int tx  = threadIdx.x;           // 0..31
    const int ty  = threadIdx.y;           // 0..7
    const int tid = ty * 32 + tx;
    const int row0 = blockIdx.x * RB;

    const int ldrow = row0 + tid;
    const bool ldok = (ldrow < N_NODES);
    const float* xrow = x + (size_t)ldrow * IN_FEAT;

    float acc[8][8] = {};

    for (int k0 = 0; k0 < IN_FEAT; k0 += KC) {
        #pragma unroll
        for (int i = 0; i < KC / 4; i++) {
            float4 v = make_float4(0.f, 0.f, 0.f, 0.f);
            if (ldok)
                v = *reinterpret_cast<const float4*>(&xrow[k0 + i * 4]);
            xs[i * 4 + 0][tid] = v.x;
            xs[i * 4 + 1][tid] = v.y;
            xs[i * 4 + 2][tid] = v.z;
            xs[i * 4 + 3][tid] = v.w;
        }
        #pragma unroll
        for (int j = 0; j < 2; j++) {
            int idx = tid + j * 256;
            int kk = idx >> 4;
            int qq = idx & 15;
            ws[kk][qq] = reinterpret_cast<const float4*>(
                             &W1[(size_t)(k0 + kk) * HIDDEN])[qq];
        }
        __syncthreads();

        #pragma unroll
        for (int k = 0; k < KC; k++) {
            float4 wa = ws[k][ty * 2];
            float4 wb = ws[k][ty * 2 + 1];
            #pragma unroll
            for (int i = 0; i < 8; i++) {
                float xv = xs[k][tx + 32 * i];
                acc[i][0] = fmaf(xv, wa.x, acc[i][0]);
                acc[i][1] = fmaf(xv, wa.y, acc[i][1]);
                acc[i][2] = fmaf(xv, wa.z, acc[i][2]);
                acc[i][3] = fmaf(xv, wa.w, acc[i][3]);
                acc[i][4] = fmaf(xv, wb.x, acc[i][4]);
                acc[i][5] = fmaf(xv, wb.y, acc[i][5]);
                acc[i][6] = fmaf(xv, wb.z, acc[i][6]);
                acc[i][7] = fmaf(xv, wb.w, acc[i][7]);
            }
        }
        __syncthreads();
    }

    #pragma unroll
    for (int i = 0; i < 8; i++) {
        int g = row0 + tx + 32 * i;
        if (g < N_NODES) {
            float* o = &g_h0[(size_t)g * HIDDEN + ty * 8];
            *reinterpret_cast<float4*>(o)     = make_float4(acc[i][0], acc[i][1], acc[i][2], acc[i][3]);
            *reinterpret_cast<float4*>(o + 4) = make_float4(acc[i][4], acc[i][5], acc[i][6], acc[i][7]);
        }
    }
}

// ---------------------------------------------------------------------------
// SpMM1 gather: g_h[n] = relu(sum_e w_e * g_h0[src_e] + b1)
// One warp per dst node; lane owns feats [2l, 2l+1].
// Edge metadata loaded lane-parallel per 32-edge chunk, shuffle-broadcast.
// ---------------------------------------------------------------------------
__global__ __launch_bounds__(256)
void spmm1_gather(const int* __restrict__ src, const float* __restrict__ ew,
                  const float* __restrict__ b1) {
    int warp = (blockIdx.x * blockDim.x + threadIdx.x) >> 5;
    int lane = threadIdx.x & 31;
    if (warp >= N_NODES) return;

    int beg = g_off[warp];
    int end = beg + g_deg[warp];

    float ax = 0.f, ay = 0.f;
    for (int j0 = beg; j0 < end; j0 += 32) {
        int j = j0 + lane;
        int e = g_eidx[(j < end) ? j : beg];
        int s = __ldg(&src[e]);
        float w = (j < end) ? __ldg(&ew[e]) : 0.f;
        int cnt = min(32, end - j0);
        #pragma unroll 4
        for (int t = 0; t < cnt; t++) {
            int   st = __shfl_sync(0xffffffffu, s, t);
            float wt = __shfl_sync(0xffffffffu, w, t);
            float2 v = *reinterpret_cast<const float2*>(
                           &g_h0[(size_t)st * HIDDEN + lane * 2]);
            ax = fmaf(v.x, wt, ax);
            ay = fmaf(v.y, wt, ay);
        }
    }
    float2 b = *reinterpret_cast<const float2*>(&b1[lane * 2]);
    float2 o;
    o.x = fmaxf(ax + b.x, 0.f);
    o.y = fmaxf(ay + b.y, 0.f);
    *reinterpret_cast<float2*>(&g_h[(size_t)warp * HIDDEN + lane * 2]) = o;
}

// ---------------------------------------------------------------------------
// GEMM2: g_z = g_h @ W2   (relu already applied). Thread per node.
// ---------------------------------------------------------------------------
__global__ __launch_bounds__(128)
void gemm2_kernel(const float* __restrict__ W2) {
    __shared__ float4 Ws[HIDDEN][N_CLASS / 4];   // 4 KB

    const int tid = threadIdx.x;
    for (int i = tid; i < HIDDEN * 4; i += 128) {
        int kk = i >> 2, qq = i & 3;
        Ws[kk][qq] = reinterpret_cast<const float4*>(&W2[(size_t)kk * N_CLASS])[qq];
    }
    __syncthreads();

    int n = blockIdx.x * 128 + tid;
    if (n >= N_NODES) return;

    float acc[N_CLASS] = {};
    const float4* hrow = reinterpret_cast<const float4*>(&g_h[(size_t)n * HIDDEN]);
    #pragma unroll
    for (int kq = 0; kq < HIDDEN / 4; kq++) {
        float4 h4 = __ldg(&hrow[kq]);
        float hv[4] = {h4.x, h4.y, h4.z, h4.w};
        #pragma unroll
        for (int j = 0; j < 4; j++) {
            int k = kq * 4 + j;
            #pragma unroll
            for (int q = 0; q < 4; q++) {
                float4 w4 = Ws[k][q];
                acc[q * 4 + 0] = fmaf(hv[j], w4.x, acc[q * 4 + 0]);
                acc[q * 4 + 1] = fmaf(hv[j], w4.y, acc[q * 4 + 1]);
                acc[q * 4 + 2] = fmaf(hv[j], w4.z, acc[q * 4 + 2]);
                acc[q * 4 + 3] = fmaf(hv[j], w4.w, acc[q * 4 + 3]);
            }
        }
    }
    float4* o = reinterpret_cast<float4*>(&g_z[(size_t)n * N_CLASS]);
    #pragma unroll
    for (int q = 0; q < 4; q++)
        o[q] = make_float4(acc[q * 4], acc[q * 4 + 1], acc[q * 4 + 2], acc[q * 4 + 3]);
}

// ---------------------------------------------------------------------------
// SpMM2: g_l[dst] += ew * g_z[src]   (16 classes, 4 lanes/edge, float4 RED)
// ---------------------------------------------------------------------------
__global__ __launch_bounds__(256)
void spmm2_kernel(const int* __restrict__ src, const int* __restrict__ dst,
                  const float* __restrict__ ew) {
    int t = blockIdx.x * blockDim.x + threadIdx.x;
    int e = t >> 2;
    int c = (t & 3) << 2;
    if (e >= N_EDGES) return;
    int s   = __ldg(&src[e]);
    int d   = __ldg(&dst[e]);
    float w = __ldg(&ew[e]);
    float4 v = *reinterpret_cast<const float4*>(&g_z[(size_t)s * N_CLASS + c]);
    red_add_v4(&g_l[(size_t)d * N_CLASS + c],
               make_float4(v.x * w, v.y * w, v.z * w, v.w * w));
}

// ---------------------------------------------------------------------------
// Softmax over 16 classes, one thread per node.
// ---------------------------------------------------------------------------
__global__ __launch_bounds__(256)
void softmax_kernel(float* __restrict__ out) {
    int n = blockIdx.x * blockDim.x + threadIdx.x;
    if (n >= N_NODES) return;
    float v[N_CLASS];
    const float4* p = reinterpret_cast<const float4*>(&g_l[(size_t)n * N_CLASS]);
    #pragma unroll
    for (int i = 0; i < 4; i++) {
        float4 q = p[i];
        v[i * 4 + 0] = q.x; v[i * 4 + 1] = q.y; v[i * 4 + 2] = q.z; v[i * 4 + 3] = q.w;
    }
    float m = v[0];
    #pragma unroll
    for (int i = 1; i < N_CLASS; i++) m = fmaxf(m, v[i]);
    float sum = 0.f;
    #pragma unroll
    for (int i = 0; i < N_CLASS; i++) { v[i] = expf(v[i] - m); sum += v[i]; }
    float inv = 1.f / sum;
    float4* o = reinterpret_cast<float4*>(&out[(size_t)n * N_CLASS]);
    #pragma unroll
    for (int i = 0; i < 4; i++) {
        o[i] = make_float4(v[i * 4] * inv, v[i * 4 + 1] * inv,
                           v[i * 4 + 2] * inv, v[i * 4 + 3] * inv);
    }
}

// ---------------------------------------------------------------------------
extern "C" void kernel_launch(void* const* d_in, const int* in_sizes, int n_in,
                              void* d_out, int out_size) {
    const float* x   = (const float*)d_in[0];
    const int*   src = (const int*)  d_in[1];
    const int*   dst = (const int*)  d_in[2];
    const float* ew  = (const float*)d_in[3];
    const float* W1  = (const float*)d_in[4];
    const float* b1  = (const float*)d_in[5];
    const float* W2  = (const float*)d_in[6];
    const float* b2  = (const float*)d_in[7];
    float* out = (float*)d_out;

    zero_kernel<<<(N_NODES * N_CLASS + 255) / 256, 256>>>(b2);
    hist_kernel<<<(N_EDGES + 255) / 256, 256>>>(dst);
    scan_kernel<<<1, SCAN_T>>>();
    fill_kernel<<<(N_EDGES + 255) / 256, 256>>>(dst);

    gemm1_kernel<<<(N_NODES + RB - 1) / RB, dim3(32, 8)>>>(x, W1);

    spmm1_gather<<<(N_NODES * 32 + 255) / 256, 256>>>(src, ew, b1);

    gemm2_kernel<<<(N_NODES + 127) / 128, 128>>>(W2);

    {
        long long threads = (long long)N_EDGES * 4;
        spmm2_kernel<<<(unsigned)((threads + 255) / 256), 256>>>(src, dst, ew);
    }
    softmax_kernel<<<(N_NODES + 255) / 256, 256>>>(out);
}

// round 4
// speedup vs baseline: 1.3684x; 1.3684x over previous
#include <cuda_runtime.h>
#include <cuda_bf16.h>

#define N_NODES 50000
#define N_EDGES 800000
#define IN_FEAT 512
#define HIDDEN  64
#define N_CLASS 16
#define KC      32
#define RB      256   // rows per block in gemm1

// Scratch (device globals — no allocation allowed)
__device__ float g_h0[N_NODES * HIDDEN];   // x @ W1
__device__ float g_h [N_NODES * HIDDEN];   // A @ h0 + b1 (pre-relu)
__device__ float g_z [N_NODES * N_CLASS];  // relu(h) @ W2
__device__ float g_l [N_NODES * N_CLASS];  // A @ z + b2 (logits)

__device__ __forceinline__ void red_add_v4(float* p, float4 v) {
    asm volatile("red.global.add.v4.f32 [%0], {%1,%2,%3,%4};"
                 :: "l"(p), "f"(v.x), "f"(v.y), "f"(v.z), "f"(v.w)
                 : "memory");
}

// ---------------------------------------------------------------------------
// init: g_h <- broadcast b1, g_l <- broadcast b2
// ---------------------------------------------------------------------------
__global__ void init_kernel(const float* __restrict__ b1,
                            const float* __restrict__ b2) {
    int i = blockIdx.x * blockDim.x + threadIdx.x;
    if (i < N_NODES * HIDDEN)  g_h[i] = b1[i & (HIDDEN - 1)];
    if (i < N_NODES * N_CLASS) g_l[i] = b2[i & (N_CLASS - 1)];
}

// ---------------------------------------------------------------------------
// GEMM1: g_h0 = x @ W1   (50000x512 @ 512x64)  -- packed f32x2 FFMA2
// Block: 256 rows x 64 cols, 256 threads (32 x 8).
// Thread (tx,ty): row-pairs {64i+2tx, 64i+2tx+1} i=0..3, cols ty*8..ty*8+7.
// xs transposed [KC][RB]; W pre-duplicated into float2{w,w} pairs.
// ---------------------------------------------------------------------------
__global__ __launch_bounds__(256, 2)
void gemm1_kernel(const float* __restrict__ x, const float* __restrict__ W1) {
    __shared__ __align__(16) float  xs[KC][RB];       // 32 KB, transposed
    __shared__ __align__(16) float2 wd[KC][HIDDEN];   // 16 KB, duplicated

    const int tx  = threadIdx.x;            // 0..31
    const int ty  = threadIdx.y;            // 0..7
    const int tid = ty * 32 + tx;
    const int row0 = blockIdx.x * RB;

    const int ldrow = row0 + tid;
    const bool ldok = (ldrow < N_NODES);
    const float* xrow = x + (size_t)ldrow * IN_FEAT;

    // acc[i][c] packs rows {64i+2tx, 64i+2tx+1} for col ty*8+c
    unsigned long long acc[4][8] = {};   // bit pattern 0 == {0.f, 0.f}

    for (int k0 = 0; k0 < IN_FEAT; k0 += KC) {
        // Stage x chunk transposed: one row per thread, 32 k-values
        #pragma unroll
        for (int i = 0; i < KC / 4; i++) {
            float4 v = make_float4(0.f, 0.f, 0.f, 0.f);
            if (ldok)
                v = *reinterpret_cast<const float4*>(&xrow[k0 + i * 4]);
            xs[i * 4 + 0][tid] = v.x;
            xs[i * 4 + 1][tid] = v.y;
            xs[i * 4 + 2][tid] = v.z;
            xs[i * 4 + 3][tid] = v.w;
        }
        // Stage W chunk duplicated: 512 float4 total, 2 per thread
        #pragma unroll
        for (int j = 0; j < 2; j++) {
            int idx = tid + j * 256;          // 0..511
            int kk = idx >> 4;                // k within chunk
            int qq = idx & 15;                // float4 within row
            float4 v = reinterpret_cast<const float4*>(
                           &W1[(size_t)(k0 + kk) * HIDDEN])[qq];
            wd[kk][qq * 4 + 0] = make_float2(v.x, v.x);
            wd[kk][qq * 4 + 1] = make_float2(v.y, v.y);
            wd[kk][qq * 4 + 2] = make_float2(v.z, v.z);
            wd[kk][qq * 4 + 3] = make_float2(v.w, v.w);
        }
        __syncthreads();

        #pragma unroll
        for (int k = 0; k < KC; k++) {
            unsigned long long xp[4];
            #pragma unroll
            for (int i = 0; i < 4; i++)
                xp[i] = *reinterpret_cast<const unsigned long long*>(
                            &xs[k][i * 64 + tx * 2]);
            #pragma unroll
            for (int c = 0; c < 8; c++) {
                unsigned long long w2 =
                    *reinterpret_cast<const unsigned long long*>(&wd[k][ty * 8 + c]);
                #pragma unroll
                for (int i = 0; i < 4; i++)
                    asm("fma.rn.f32x2 %0, %1, %2, %0;"
                        : "+l"(acc[i][c]) : "l"(xp[i]), "l"(w2));
            }
        }
        __syncthreads();
    }

    #pragma unroll
    for (int i = 0; i < 4; i++) {
        int r = row0 + i * 64 + tx * 2;
        float lo[8], hi[8];
        #pragma unroll
        for (int c = 0; c < 8; c++) {
            float2 f = *reinterpret_cast<float2*>(&acc[i][c]);
            lo[c] = f.x; hi[c] = f.y;
        }
        if (r < N_NODES) {
            float4* o = reinterpret_cast<float4*>(&g_h0[(size_t)r * HIDDEN + ty * 8]);
            o[0] = make_float4(lo[0], lo[1], lo[2], lo[3]);
            o[1] = make_float4(lo[4], lo[5], lo[6], lo[7]);
        }
        if (r + 1 < N_NODES) {
            float4* o = reinterpret_cast<float4*>(&g_h0[(size_t)(r + 1) * HIDDEN + ty * 8]);
            o[0] = make_float4(hi[0], hi[1], hi[2], hi[3]);
            o[1] = make_float4(hi[4], hi[5], hi[6], hi[7]);
        }
    }
}

// ---------------------------------------------------------------------------
// SpMM1: g_h[dst] += ew * g_h0[src]   (64 feats, 16 lanes/edge, float4 RED)
// ---------------------------------------------------------------------------
__global__ __launch_bounds__(256)
void spmm1_kernel(const int* __restrict__ src, const int* __restrict__ dst,
                  const float* __restrict__ ew) {
    int t = blockIdx.x * blockDim.x + threadIdx.x;
    int e = t >> 4;
    int f = (t & 15) << 2;
    if (e >= N_EDGES) return;
    int s   = __ldg(&src[e]);
    int d   = __ldg(&dst[e]);
    float w = __ldg(&ew[e]);
    float4 v = *reinterpret_cast<const float4*>(&g_h0[(size_t)s * HIDDEN + f]);
    red_add_v4(&g_h[(size_t)d * HIDDEN + f],
               make_float4(v.x * w, v.y * w, v.z * w, v.w * w));
}

// ---------------------------------------------------------------------------
// GEMM2: g_z = relu(g_h) @ W2   (50000x64 @ 64x16), thread per node.
// 64-thread blocks for occupancy (782 blocks).
// ---------------------------------------------------------------------------
__global__ __launch_bounds__(64)
void gemm2_kernel(const float* __restrict__ W2) {
    __shared__ float4 Ws[HIDDEN][N_CLASS / 4];   // 4 KB

    const int tid = threadIdx.x;
    #pragma unroll
    for (int j = 0; j < 4; j++) {
        int i = tid + j * 64;          // 0..255 float4
        int kk = i >> 2, qq = i & 3;
        Ws[kk][qq] = reinterpret_cast<const float4*>(&W2[(size_t)kk * N_CLASS])[qq];
    }
    __syncthreads();

    int n = blockIdx.x * 64 + tid;
    if (n >= N_NODES) return;

    float acc[N_CLASS] = {};
    const float4* hrow = reinterpret_cast<const float4*>(&g_h[(size_t)n * HIDDEN]);
    #pragma unroll
    for (int kq = 0; kq < HIDDEN / 4; kq++) {
        float4 h4 = __ldg(&hrow[kq]);
        float hv[4] = {fmaxf(h4.x, 0.f), fmaxf(h4.y, 0.f),
                       fmaxf(h4.z, 0.f), fmaxf(h4.w, 0.f)};
        #pragma unroll
        for (int j = 0; j < 4; j++) {
            int k = kq * 4 + j;
            #pragma unroll
            for (int q = 0; q < 4; q++) {
                float4 w4 = Ws[k][q];
                acc[q * 4 + 0] = fmaf(hv[j], w4.x, acc[q * 4 + 0]);
                acc[q * 4 + 1] = fmaf(hv[j], w4.y, acc[q * 4 + 1]);
                acc[q * 4 + 2] = fmaf(hv[j], w4.z, acc[q * 4 + 2]);
                acc[q * 4 + 3] = fmaf(hv[j], w4.w, acc[q * 4 + 3]);
            }
        }
    }
    float4* o = reinterpret_cast<float4*>(&g_z[(size_t)n * N_CLASS]);
    #pragma unroll
    for (int q = 0; q < 4; q++)
        o[q] = make_float4(acc[q * 4], acc[q * 4 + 1], acc[q * 4 + 2], acc[q * 4 + 3]);
}

// ---------------------------------------------------------------------------
// SpMM2: g_l[dst] += ew * g_z[src]   (16 classes, 4 lanes/edge, float4 RED)
// ---------------------------------------------------------------------------
__global__ __launch_bounds__(256)
void spmm2_kernel(const int* __restrict__ src, const int* __restrict__ dst,
                  const float* __restrict__ ew) {
    int t = blockIdx.x * blockDim.x + threadIdx.x;
    int e = t >> 2;
    int c = (t & 3) << 2;
    if (e >= N_EDGES) return;
    int s   = __ldg(&src[e]);
    int d   = __ldg(&dst[e]);
    float w = __ldg(&ew[e]);
    float4 v = *reinterpret_cast<const float4*>(&g_z[(size_t)s * N_CLASS + c]);
    red_add_v4(&g_l[(size_t)d * N_CLASS + c],
               make_float4(v.x * w, v.y * w, v.z * w, v.w * w));
}

// ---------------------------------------------------------------------------
// Softmax over 16 classes, one thread per node.
// ---------------------------------------------------------------------------
__global__ __launch_bounds__(256)
void softmax_kernel(float* __restrict__ out) {
    int n = blockIdx.x * blockDim.x + threadIdx.x;
    if (n >= N_NODES) return;
    float v[N_CLASS];
    const float4* p = reinterpret_cast<const float4*>(&g_l[(size_t)n * N_CLASS]);
    #pragma unroll
    for (int i = 0; i < 4; i++) {
        float4 q = p[i];
        v[i * 4 + 0] = q.x; v[i * 4 + 1] = q.y; v[i * 4 + 2] = q.z; v[i * 4 + 3] = q.w;
    }
    float m = v[0];
    #pragma unroll
    for (int i = 1; i < N_CLASS; i++) m = fmaxf(m, v[i]);
    float sum = 0.f;
    #pragma unroll
    for (int i = 0; i < N_CLASS; i++) { v[i] = expf(v[i] - m); sum += v[i]; }
    float inv = 1.f / sum;
    float4* o = reinterpret_cast<float4*>(&out[(size_t)n * N_CLASS]);
    #pragma unroll
    for (int i = 0; i < 4; i++) {
        o[i] = make_float4(v[i * 4] * inv, v[i * 4 + 1] * inv,
                           v[i * 4 + 2] * inv, v[i * 4 + 3] * inv);
    }
}

// ---------------------------------------------------------------------------
extern "C" void kernel_launch(void* const* d_in, const int* in_sizes, int n_in,
                              void* d_out, int out_size) {
    const float* x   = (const float*)d_in[0];
    const int*   src = (const int*)  d_in[1];
    const int*   dst = (const int*)  d_in[2];
    const float* ew  = (const float*)d_in[3];
    const float* W1  = (const float*)d_in[4];
    const float* b1  = (const float*)d_in[5];
    const float* W2  = (const float*)d_in[6];
    const float* b2  = (const float*)d_in[7];
    float* out = (float*)d_out;

    {
        int total = N_NODES * HIDDEN;
        init_kernel<<<(total + 255) / 256, 256>>>(b1, b2);
    }
    gemm1_kernel<<<(N_NODES + RB - 1) / RB, dim3(32, 8)>>>(x, W1);
    {
        long long threads = (long long)N_EDGES * 16;
        spmm1_kernel<<<(unsigned)((threads + 255) / 256), 256>>>(src, dst, ew);
    }
    gemm2_kernel<<<(N_NODES + 63) / 64, 64>>>(W2);
    {
        long long threads = (long long)N_EDGES * 4;
        spmm2_kernel<<<(unsigned)((threads + 255) / 256), 256>>>(src, dst, ew);
    }
    softmax_kernel<<<(N_NODES + 255) / 256, 256>>>(out);
}

// round 6
// speedup vs baseline: 1.6182x; 1.1825x over previous
#include <cuda_runtime.h>
#include <cuda_bf16.h>
#include <cstdint>

#define N_NODES 50000
#define N_EDGES 800000
#define IN_FEAT 512
#define HIDDEN  64
#define N_CLASS 16
#define KC      32
#define RB      128   // rows per block in gemm1

// Scratch (device globals — no allocation allowed)
__device__ float g_h0[N_NODES * HIDDEN];   // x @ W1
__device__ float g_h [N_NODES * HIDDEN];   // A @ h0 + b1 (pre-relu)
__device__ float g_z [N_NODES * N_CLASS];  // relu(h) @ W2
__device__ float g_l [N_NODES * N_CLASS];  // A @ z + b2 (logits)

__device__ __forceinline__ void red_add_v4(float* p, float4 v) {
    asm volatile("red.global.add.v4.f32 [%0], {%1,%2,%3,%4};"
                 :: "l"(p), "f"(v.x), "f"(v.y), "f"(v.z), "f"(v.w)
                 : "memory");
}

// ---------------------------------------------------------------------------
// init_h: g_h <- broadcast b1      (launch #1)
// ---------------------------------------------------------------------------
__global__ void init_h_kernel(const float* __restrict__ b1) {
    int i = blockIdx.x * blockDim.x + threadIdx.x;
    if (i < N_NODES * HIDDEN) g_h[i] = b1[i & (HIDDEN - 1)];
}

// ---------------------------------------------------------------------------
// init_l: g_l <- broadcast b2      (launch #2)
// ---------------------------------------------------------------------------
__global__ void init_l_kernel(const float* __restrict__ b2) {
    int i = blockIdx.x * blockDim.x + threadIdx.x;
    if (i < N_NODES * N_CLASS) g_l[i] = b2[i & (N_CLASS - 1)];
}

// ---------------------------------------------------------------------------
// GEMM1: g_h0 = x @ W1   (50000x512 @ 512x64)  -- packed f32x2 FFMA2
// Block: 128 rows x 64 cols, 256 threads (32 x 8).
// Thread (tx,ty): row-pairs {2tx,2tx+1} and {64+2tx,64+2tx+1},
//                 cols ty*8..ty*8+7.  acc = 16 x u64 (32 regs).
// xs transposed [KC][RB]; W duplicated into float2{w,w}, read as 16B pairs.
// ---------------------------------------------------------------------------
__global__ __launch_bounds__(256)
void gemm1_kernel(const float* __restrict__ x, const float* __restrict__ W1) {
    __shared__ __align__(16) float  xs[KC][RB];       // 16 KB, transposed
    __shared__ __align__(16) float2 wd[KC][HIDDEN];   // 16 KB, duplicated

    const int tx  = threadIdx.x;            // 0..31
    const int ty  = threadIdx.y;            // 0..7
    const int tid = ty * 32 + tx;
    const int row0 = blockIdx.x * RB;

    // Staging assignment: 2 threads per row; thread stages 16 k-values
    const int strow = tid >> 1;              // 0..127
    const int sthalf = tid & 1;              // which 16-k half
    int grow = row0 + strow;
    if (grow >= N_NODES) grow = N_NODES - 1; // clamp (output masked later)
    const float* xrow = x + (size_t)grow * IN_FEAT;

    unsigned long long acc0[8] = {};   // rows {2tx, 2tx+1}
    unsigned long long acc1[8] = {};   // rows {64+2tx, 64+2tx+1}

    for (int k0 = 0; k0 < IN_FEAT; k0 += KC) {
        // Stage x transposed: 4 float4 per thread
        #pragma unroll
        for (int q = 0; q < 4; q++) {
            int kk = sthalf * 16 + q * 4;
            float4 v = *reinterpret_cast<const float4*>(&xrow[k0 + kk]);
            xs[kk + 0][strow] = v.x;
            xs[kk + 1][strow] = v.y;
            xs[kk + 2][strow] = v.z;
            xs[kk + 3][strow] = v.w;
        }
        // Stage W duplicated: 2048 float2, 8 per thread (coalesced reads)
        #pragma unroll
        for (int i = 0; i < 8; i++) {
            int idx = tid + i * 256;          // 0..2047
            int kk  = idx >> 6;
            int col = idx & 63;
            float w = W1[(size_t)(k0 + kk) * HIDDEN + col];
            wd[kk][col] = make_float2(w, w);
        }
        __syncthreads();

        #pragma unroll
        for (int k = 0; k < KC; k++) {
            unsigned long long xp0 =
                *reinterpret_cast<const unsigned long long*>(&xs[k][2 * tx]);
            unsigned long long xp1 =
                *reinterpret_cast<const unsigned long long*>(&xs[k][64 + 2 * tx]);
            const ulonglong2* wrow =
                reinterpret_cast<const ulonglong2*>(&wd[k][ty * 8]);
            #pragma unroll
            for (int q = 0; q < 4; q++) {
                ulonglong2 w2 = wrow[q];      // cols 2q, 2q+1 (dup'd), broadcast
                asm("fma.rn.f32x2 %0, %1, %2, %0;" : "+l"(acc0[2*q])   : "l"(xp0), "l"(w2.x));
                asm("fma.rn.f32x2 %0, %1, %2, %0;" : "+l"(acc0[2*q+1]) : "l"(xp0), "l"(w2.y));
                asm("fma.rn.f32x2 %0, %1, %2, %0;" : "+l"(acc1[2*q])   : "l"(xp1), "l"(w2.x));
                asm("fma.rn.f32x2 %0, %1, %2, %0;" : "+l"(acc1[2*q+1]) : "l"(xp1), "l"(w2.y));
            }
        }
        __syncthreads();
    }

    // Epilogue: unpack row-pairs, write float4s
    #pragma unroll
    for (int i = 0; i < 2; i++) {
        const unsigned long long* a = (i == 0) ? acc0 : acc1;
        int r = row0 + i * 64 + tx * 2;
        float lo[8], hi[8];
        #pragma unroll
        for (int c = 0; c < 8; c++) {
            float2 f = *reinterpret_cast<const float2*>(&a[c]);
            lo[c] = f.x; hi[c] = f.y;
        }
        if (r < N_NODES) {
            float4* o = reinterpret_cast<float4*>(&g_h0[(size_t)r * HIDDEN + ty * 8]);
            o[0] = make_float4(lo[0], lo[1], lo[2], lo[3]);
            o[1] = make_float4(lo[4], lo[5], lo[6], lo[7]);
        }
        if (r + 1 < N_NODES) {
            float4* o = reinterpret_cast<float4*>(&g_h0[(size_t)(r + 1) * HIDDEN + ty * 8]);
            o[0] = make_float4(hi[0], hi[1], hi[2], hi[3]);
            o[1] = make_float4(hi[4], hi[5], hi[6], hi[7]);
        }
    }
}

// ---------------------------------------------------------------------------
// SpMM1: g_h[dst] += ew * g_h0[src]   (64 feats, 16 lanes/edge, float4 RED)
// Launch #4 -> gets profiled by ncu.
// ---------------------------------------------------------------------------
__global__ __launch_bounds__(256)
void spmm1_kernel(const int* __restrict__ src, const int* __restrict__ dst,
                  const float* __restrict__ ew) {
    int t = blockIdx.x * blockDim.x + threadIdx.x;
    int e = t >> 4;
    int f = (t & 15) << 2;
    if (e >= N_EDGES) return;
    int s   = __ldg(&src[e]);
    int d   = __ldg(&dst[e]);
    float w = __ldg(&ew[e]);
    float4 v = *reinterpret_cast<const float4*>(&g_h0[(size_t)s * HIDDEN + f]);
    red_add_v4(&g_h[(size_t)d * HIDDEN + f],
               make_float4(v.x * w, v.y * w, v.z * w, v.w * w));
}

// ---------------------------------------------------------------------------
// GEMM2: g_z = relu(g_h) @ W2   (50000x64 @ 64x16), thread per node.
// ---------------------------------------------------------------------------
__global__ __launch_bounds__(64)
void gemm2_kernel(const float* __restrict__ W2) {
    __shared__ float4 Ws[HIDDEN][N_CLASS / 4];   // 4 KB

    const int tid = threadIdx.x;
    #pragma unroll
    for (int j = 0; j < 4; j++) {
        int i = tid + j * 64;
        int kk = i >> 2, qq = i & 3;
        Ws[kk][qq] = reinterpret_cast<const float4*>(&W2[(size_t)kk * N_CLASS])[qq];
    }
    __syncthreads();

    int n = blockIdx.x * 64 + tid;
    if (n >= N_NODES) return;

    float acc[N_CLASS] = {};
    const float4* hrow = reinterpret_cast<const float4*>(&g_h[(size_t)n * HIDDEN]);
    #pragma unroll
    for (int kq = 0; kq < HIDDEN / 4; kq++) {
        float4 h4 = __ldg(&hrow[kq]);
        float hv[4] = {fmaxf(h4.x, 0.f), fmaxf(h4.y, 0.f),
                       fmaxf(h4.z, 0.f), fmaxf(h4.w, 0.f)};
        #pragma unroll
        for (int j = 0; j < 4; j++) {
            int k = kq * 4 + j;
            #pragma unroll
            for (int q = 0; q < 4; q++) {
                float4 w4 = Ws[k][q];
                acc[q * 4 + 0] = fmaf(hv[j], w4.x, acc[q * 4 + 0]);
                acc[q * 4 + 1] = fmaf(hv[j], w4.y, acc[q * 4 + 1]);
                acc[q * 4 + 2] = fmaf(hv[j], w4.z, acc[q * 4 + 2]);
                acc[q * 4 + 3] = fmaf(hv[j], w4.w, acc[q * 4 + 3]);
            }
        }
    }
    float4* o = reinterpret_cast<float4*>(&g_z[(size_t)n * N_CLASS]);
    #pragma unroll
    for (int q = 0; q < 4; q++)
        o[q] = make_float4(acc[q * 4], acc[q * 4 + 1], acc[q * 4 + 2], acc[q * 4 + 3]);
}

// ---------------------------------------------------------------------------
// SpMM2: g_l[dst] += ew * g_z[src]   (16 classes, 4 lanes/edge, float4 RED)
// ---------------------------------------------------------------------------
__global__ __launch_bounds__(256)
void spmm2_kernel(const int* __restrict__ src, const int* __restrict__ dst,
                  const float* __restrict__ ew) {
    int t = blockIdx.x * blockDim.x + threadIdx.x;
    int e = t >> 2;
    int c = (t & 3) << 2;
    if (e >= N_EDGES) return;
    int s   = __ldg(&src[e]);
    int d   = __ldg(&dst[e]);
    float w = __ldg(&ew[e]);
    float4 v = *reinterpret_cast<const float4*>(&g_z[(size_t)s * N_CLASS + c]);
    red_add_v4(&g_l[(size_t)d * N_CLASS + c],
               make_float4(v.x * w, v.y * w, v.z * w, v.w * w));
}

// ---------------------------------------------------------------------------
// Softmax over 16 classes, one thread per node.
// ---------------------------------------------------------------------------
__global__ __launch_bounds__(256)
void softmax_kernel(float* __restrict__ out) {
    int n = blockIdx.x * blockDim.x + threadIdx.x;
    if (n >= N_NODES) return;
    float v[N_CLASS];
    const float4* p = reinterpret_cast<const float4*>(&g_l[(size_t)n * N_CLASS]);
    #pragma unroll
    for (int i = 0; i < 4; i++) {
        float4 q = p[i];
        v[i * 4 + 0] = q.x; v[i * 4 + 1] = q.y; v[i * 4 + 2] = q.z; v[i * 4 + 3] = q.w;
    }
    float m = v[0];
    #pragma unroll
    for (int i = 1; i < N_CLASS; i++) m = fmaxf(m, v[i]);
    float sum = 0.f;
    #pragma unroll
    for (int i = 0; i < N_CLASS; i++) { v[i] = expf(v[i] - m); sum += v[i]; }
    float inv = 1.f / sum;
    float4* o = reinterpret_cast<float4*>(&out[(size_t)n * N_CLASS]);
    #pragma unroll
    for (int i = 0; i < 4; i++) {
        o[i] = make_float4(v[i * 4] * inv, v[i * 4 + 1] * inv,
                           v[i * 4 + 2] * inv, v[i * 4 + 3] * inv);
    }
}

// ---------------------------------------------------------------------------
extern "C" void kernel_launch(void* const* d_in, const int* in_sizes, int n_in,
                              void* d_out, int out_size) {
    const float* x   = (const float*)d_in[0];
    const int*   src = (const int*)  d_in[1];
    const int*   dst = (const int*)  d_in[2];
    const float* ew  = (const float*)d_in[3];
    const float* W1  = (const float*)d_in[4];
    const float* b1  = (const float*)d_in[5];
    const float* W2  = (const float*)d_in[6];
    const float* b2  = (const float*)d_in[7];
    float* out = (float*)d_out;

    // #1, #2: bias broadcasts (split so spmm1 is launch #4 for profiling)
    init_h_kernel<<<(N_NODES * HIDDEN + 255) / 256, 256>>>(b1);
    init_l_kernel<<<(N_NODES * N_CLASS + 255) / 256, 256>>>(b2);

    // #3
    gemm1_kernel<<<(N_NODES + RB - 1) / RB, dim3(32, 8)>>>(x, W1);

    // #4  (profiled)
    {
        long long threads = (long long)N_EDGES * 16;
        spmm1_kernel<<<(unsigned)((threads + 255) / 256), 256>>>(src, dst, ew);
    }
    // #5
    gemm2_kernel<<<(N_NODES + 63) / 64, 64>>>(W2);
    // #6
    {
        long long threads = (long long)N_EDGES * 4;
        spmm2_kernel<<<(unsigned)((threads + 255) / 256), 256>>>(src, dst, ew);
    }
    // #7
    softmax_kernel<<<(N_NODES + 255) / 256, 256>>>(out);
}

// round 7
// speedup vs baseline: 1.6683x; 1.0310x over previous
#include <cuda_runtime.h>
#include <cuda_bf16.h>
#include <cstdint>

#define N_NODES 50000
#define N_EDGES 800000
#define IN_FEAT 512
#define HIDDEN  64
#define N_CLASS 16
#define KC      32
#define RB      128   // rows per block in gemm1
#define NCHUNK  (IN_FEAT / KC)

// Scratch (device globals — no allocation allowed)
__device__ float g_h0[N_NODES * HIDDEN];   // x @ W1
__device__ float g_h [N_NODES * HIDDEN];   // A @ h0 + b1 (pre-relu)
__device__ float g_z [N_NODES * N_CLASS];  // relu(h) @ W2
__device__ float g_l [N_NODES * N_CLASS];  // A @ z + b2 (logits)

__device__ __forceinline__ void red_add_v4(float* p, float4 v) {
    asm volatile("red.global.add.v4.f32 [%0], {%1,%2,%3,%4};"
                 :: "l"(p), "f"(v.x), "f"(v.y), "f"(v.z), "f"(v.w)
                 : "memory");
}

// ---------------------------------------------------------------------------
// init_h: g_h <- broadcast b1                       (launch #1)
// ---------------------------------------------------------------------------
__global__ void init_h_kernel(const float* __restrict__ b1) {
    int i = blockIdx.x * blockDim.x + threadIdx.x;
    if (i < N_NODES * HIDDEN) g_h[i] = b1[i & (HIDDEN - 1)];
}

// ---------------------------------------------------------------------------
// init_l halves: g_l <- broadcast b2                (launches #2, #3)
// ---------------------------------------------------------------------------
__global__ void init_l_kernel(const float* __restrict__ b2, int base) {
    int i = base + blockIdx.x * blockDim.x + threadIdx.x;
    if (i < N_NODES * N_CLASS) g_l[i] = b2[i & (N_CLASS - 1)];
}

// ---------------------------------------------------------------------------
// GEMM1: g_h0 = x @ W1   (50000x512 @ 512x64)  -- FFMA2, double-buffered
// Block: 128 rows x 64 cols, 256 threads (32 x 8).         (launch #4)
// Thread (tx,ty): row-pairs {2tx,2tx+1},{64+2tx,64+2tx+1}, cols ty*8..+7.
// Register-staged: LDG chunk c+1 -> compute c -> STS c+1 -> 1 sync.
// ---------------------------------------------------------------------------
__global__ __launch_bounds__(256)
void gemm1_kernel(const float* __restrict__ x, const float* __restrict__ W1) {
    __shared__ __align__(16) float  xs[2][KC][RB];       // 32 KB
    __shared__ __align__(16) float2 wd[2][KC][HIDDEN];   // 32 KB

    const int tx  = threadIdx.x;            // 0..31
    const int ty  = threadIdx.y;            // 0..7
    const int tid = ty * 32 + tx;
    const int row0 = blockIdx.x * RB;

    // Staging: 2 threads per x row; thread stages 16 k-values of its row
    const int strow  = tid >> 1;
    const int sthalf = tid & 1;
    int grow = row0 + strow;
    if (grow >= N_NODES) grow = N_NODES - 1;   // clamp; masked at output
    const float* xrow = x + (size_t)grow * IN_FEAT + sthalf * 16;
    // W staging: 2 float4 per thread
    const int wkk0 = tid >> 4;                 // k of first float4
    const int wqq  = tid & 15;

    float4 xr[4];
    float4 wr[2];

    auto ld = [&](int c) {
        const int k0 = c * KC;
        #pragma unroll
        for (int q = 0; q < 4; q++)
            xr[q] = __ldg(reinterpret_cast<const float4*>(&xrow[k0 + q * 4]));
        #pragma unroll
        for (int j = 0; j < 2; j++)
            wr[j] = __ldg(reinterpret_cast<const float4*>(
                        &W1[(size_t)(k0 + wkk0 + j * 16) * HIDDEN + wqq * 4]));
    };
    auto st = [&](int b) {
        #pragma unroll
        for (int q = 0; q < 4; q++) {
            int kk = sthalf * 16 + q * 4;
            xs[b][kk + 0][strow] = xr[q].x;
            xs[b][kk + 1][strow] = xr[q].y;
            xs[b][kk + 2][strow] = xr[q].z;
            xs[b][kk + 3][strow] = xr[q].w;
        }
        #pragma unroll
        for (int j = 0; j < 2; j++) {
            float2* wp = &wd[b][wkk0 + j * 16][wqq * 4];
            wp[0] = make_float2(wr[j].x, wr[j].x);
            wp[1] = make_float2(wr[j].y, wr[j].y);
            wp[2] = make_float2(wr[j].z, wr[j].z);
            wp[3] = make_float2(wr[j].w, wr[j].w);
        }
    };

    unsigned long long acc0[8] = {};
    unsigned long long acc1[8] = {};

    ld(0); st(0);
    __syncthreads();

    for (int c = 0; c < NCHUNK; c++) {
        const int cb = c & 1;
        if (c + 1 < NCHUNK) ld(c + 1);          // LDGs overlap compute below

        #pragma unroll
        for (int k = 0; k < KC; k++) {
            unsigned long long xp0 =
                *reinterpret_cast<const unsigned long long*>(&xs[cb][k][2 * tx]);
            unsigned long long xp1 =
                *reinterpret_cast<const unsigned long long*>(&xs[cb][k][64 + 2 * tx]);
            const ulonglong2* wrow =
                reinterpret_cast<const ulonglong2*>(&wd[cb][k][ty * 8]);
            #pragma unroll
            for (int q = 0; q < 4; q++) {
                ulonglong2 w2 = wrow[q];
                asm("fma.rn.f32x2 %0, %1, %2, %0;" : "+l"(acc0[2*q])   : "l"(xp0), "l"(w2.x));
                asm("fma.rn.f32x2 %0, %1, %2, %0;" : "+l"(acc0[2*q+1]) : "l"(xp0), "l"(w2.y));
                asm("fma.rn.f32x2 %0, %1, %2, %0;" : "+l"(acc1[2*q])   : "l"(xp1), "l"(w2.x));
                asm("fma.rn.f32x2 %0, %1, %2, %0;" : "+l"(acc1[2*q+1]) : "l"(xp1), "l"(w2.y));
            }
        }

        if (c + 1 < NCHUNK) st((c + 1) & 1);    // other buffer: safe pre-sync
        __syncthreads();
    }

    #pragma unroll
    for (int i = 0; i < 2; i++) {
        const unsigned long long* a = (i == 0) ? acc0 : acc1;
        int r = row0 + i * 64 + tx * 2;
        float lo[8], hi[8];
        #pragma unroll
        for (int c = 0; c < 8; c++) {
            float2 f = *reinterpret_cast<const float2*>(&a[c]);
            lo[c] = f.x; hi[c] = f.y;
        }
        if (r < N_NODES) {
            float4* o = reinterpret_cast<float4*>(&g_h0[(size_t)r * HIDDEN + ty * 8]);
            o[0] = make_float4(lo[0], lo[1], lo[2], lo[3]);
            o[1] = make_float4(lo[4], lo[5], lo[6], lo[7]);
        }
        if (r + 1 < N_NODES) {
            float4* o = reinterpret_cast<float4*>(&g_h0[(size_t)(r + 1) * HIDDEN + ty * 8]);
            o[0] = make_float4(hi[0], hi[1], hi[2], hi[3]);
            o[1] = make_float4(hi[4], hi[5], hi[6], hi[7]);
        }
    }
}

// ---------------------------------------------------------------------------
// SpMM1: g_h[dst] += ew * g_h0[src]   (64 feats, 16 lanes/edge, float4 RED)
// ---------------------------------------------------------------------------
__global__ __launch_bounds__(256)
void spmm1_kernel(const int* __restrict__ src, const int* __restrict__ dst,
                  const float* __restrict__ ew) {
    int t = blockIdx.x * blockDim.x + threadIdx.x;
    int e = t >> 4;
    int f = (t & 15) << 2;
    if (e >= N_EDGES) return;
    int s   = __ldg(&src[e]);
    int d   = __ldg(&dst[e]);
    float w = __ldg(&ew[e]);
    float4 v = *reinterpret_cast<const float4*>(&g_h0[(size_t)s * HIDDEN + f]);
    red_add_v4(&g_h[(size_t)d * HIDDEN + f],
               make_float4(v.x * w, v.y * w, v.z * w, v.w * w));
}

// ---------------------------------------------------------------------------
// GEMM2: g_z = relu(g_h) @ W2   (50000x64 @ 64x16), thread per node.
// ---------------------------------------------------------------------------
__global__ __launch_bounds__(64)
void gemm2_kernel(const float* __restrict__ W2) {
    __shared__ float4 Ws[HIDDEN][N_CLASS / 4];   // 4 KB

    const int tid = threadIdx.x;
    #pragma unroll
    for (int j = 0; j < 4; j++) {
        int i = tid + j * 64;
        int kk = i >> 2, qq = i & 3;
        Ws[kk][qq] = reinterpret_cast<const float4*>(&W2[(size_t)kk * N_CLASS])[qq];
    }
    __syncthreads();

    int n = blockIdx.x * 64 + tid;
    if (n >= N_NODES) return;

    float acc[N_CLASS] = {};
    const float4* hrow = reinterpret_cast<const float4*>(&g_h[(size_t)n * HIDDEN]);
    #pragma unroll
    for (int kq = 0; kq < HIDDEN / 4; kq++) {
        float4 h4 = __ldg(&hrow[kq]);
        float hv[4] = {fmaxf(h4.x, 0.f), fmaxf(h4.y, 0.f),
                       fmaxf(h4.z, 0.f), fmaxf(h4.w, 0.f)};
        #pragma unroll
        for (int j = 0; j < 4; j++) {
            int k = kq * 4 + j;
            #pragma unroll
            for (int q = 0; q < 4; q++) {
                float4 w4 = Ws[k][q];
                acc[q * 4 + 0] = fmaf(hv[j], w4.x, acc[q * 4 + 0]);
                acc[q * 4 + 1] = fmaf(hv[j], w4.y, acc[q * 4 + 1]);
                acc[q * 4 + 2] = fmaf(hv[j], w4.z, acc[q * 4 + 2]);
                acc[q * 4 + 3] = fmaf(hv[j], w4.w, acc[q * 4 + 3]);
            }
        }
    }
    float4* o = reinterpret_cast<float4*>(&g_z[(size_t)n * N_CLASS]);
    #pragma unroll
    for (int q = 0; q < 4; q++)
        o[q] = make_float4(acc[q * 4], acc[q * 4 + 1], acc[q * 4 + 2], acc[q * 4 + 3]);
}

// ---------------------------------------------------------------------------
// SpMM2: g_l[dst] += ew * g_z[src]   (16 classes, 4 lanes/edge, float4 RED)
// ---------------------------------------------------------------------------
__global__ __launch_bounds__(256)
void spmm2_kernel(const int* __restrict__ src, const int* __restrict__ dst,
                  const float* __restrict__ ew) {
    int t = blockIdx.x * blockDim.x + threadIdx.x;
    int e = t >> 2;
    int c = (t & 3) << 2;
    if (e >= N_EDGES) return;
    int s   = __ldg(&src[e]);
    int d   = __ldg(&dst[e]);
    float w = __ldg(&ew[e]);
    float4 v = *reinterpret_cast<const float4*>(&g_z[(size_t)s * N_CLASS + c]);
    red_add_v4(&g_l[(size_t)d * N_CLASS + c],
               make_float4(v.x * w, v.y * w, v.z * w, v.w * w));
}

// ---------------------------------------------------------------------------
// Softmax over 16 classes, one thread per node.
// ---------------------------------------------------------------------------
__global__ __launch_bounds__(256)
void softmax_kernel(float* __restrict__ out) {
    int n = blockIdx.x * blockDim.x + threadIdx.x;
    if (n >= N_NODES) return;
    float v[N_CLASS];
    const float4* p = reinterpret_cast<const float4*>(&g_l[(size_t)n * N_CLASS]);
    #pragma unroll
    for (int i = 0; i < 4; i++) {
        float4 q = p[i];
        v[i * 4 + 0] = q.x; v[i * 4 + 1] = q.y; v[i * 4 + 2] = q.z; v[i * 4 + 3] = q.w;
    }
    float m = v[0];
    #pragma unroll
    for (int i = 1; i < N_CLASS; i++) m = fmaxf(m, v[i]);
    float sum = 0.f;
    #pragma unroll
    for (int i = 0; i < N_CLASS; i++) { v[i] = __expf(v[i] - m); sum += v[i]; }
    float inv = 1.f / sum;
    float4* o = reinterpret_cast<float4*>(&out[(size_t)n * N_CLASS]);
    #pragma unroll
    for (int i = 0; i < 4; i++) {
        o[i] = make_float4(v[i * 4] * inv, v[i * 4 + 1] * inv,
                           v[i * 4 + 2] * inv, v[i * 4 + 3] * inv);
    }
}

// ---------------------------------------------------------------------------
extern "C" void kernel_launch(void* const* d_in, const int* in_sizes, int n_in,
                              void* d_out, int out_size) {
    const float* x   = (const float*)d_in[0];
    const int*   src = (const int*)  d_in[1];
    const int*   dst = (const int*)  d_in[2];
    const float* ew  = (const float*)d_in[3];
    const float* W1  = (const float*)d_in[4];
    const float* b1  = (const float*)d_in[5];
    const float* W2  = (const float*)d_in[6];
    const float* b2  = (const float*)d_in[7];
    float* out = (float*)d_out;

    const int HALF_L = (N_NODES * N_CLASS) / 2;

    // #1..#3: bias broadcasts (3 launches so gemm1 lands at profiled slot #4)
    init_h_kernel<<<(N_NODES * HIDDEN + 255) / 256, 256>>>(b1);
    init_l_kernel<<<(HALF_L + 255) / 256, 256>>>(b2, 0);
    init_l_kernel<<<(HALF_L + 255) / 256, 256>>>(b2, HALF_L);

    // #4  (profiled)
    gemm1_kernel<<<(N_NODES + RB - 1) / RB, dim3(32, 8)>>>(x, W1);

    // #5
    {
        long long threads = (long long)N_EDGES * 16;
        spmm1_kernel<<<(unsigned)((threads + 255) / 256), 256>>>(src, dst, ew);
    }
    // #6
    gemm2_kernel<<<(N_NODES + 63) / 64, 64>>>(W2);
    // #7
    {
        long long threads = (long long)N_EDGES * 4;
        spmm2_kernel<<<(unsigned)((threads + 255) / 256), 256>>>(src, dst, ew);
    }
    // #8
    softmax_kernel<<<(N_NODES + 255) / 256, 256>>>(out);
}